// round 3
// baseline (speedup 1.0000x reference)
#include <cuda_runtime.h>
#include <cuda_fp16.h>
#include <cstdint>

// LSTM discriminator: B=2048, T=512, H=128, input dim 1.
// Persistent kernel: 128 CTAs x 256 threads, each CTA owns 16 batch rows.
// W_hh held as f16 mma B-fragments in registers for the whole kernel.
// h(t) exchanged through double-buffered SMEM (f16), one barrier per step.

#define T_STEPS 512
#define HDIM    128
#define MB      16
#define HSTR    136   // padded stride in halves (272B) -> conflict-free LDS

__device__ __forceinline__ float tanh_approx(float x) {
    float y;
    asm("tanh.approx.f32 %0, %1;" : "=f"(y) : "f"(x));
    return y;
}
__device__ __forceinline__ float sigmoid_fast(float x) {
    return fmaf(tanh_approx(0.5f * x), 0.5f, 0.5f);
}

__device__ __forceinline__ void mma16816(float d[4], const uint32_t a[4], const uint32_t b[2]) {
    asm volatile(
        "mma.sync.aligned.m16n8k16.row.col.f32.f16.f16.f32 "
        "{%0,%1,%2,%3}, {%4,%5,%6,%7}, {%8,%9}, {%0,%1,%2,%3};\n"
        : "+f"(d[0]), "+f"(d[1]), "+f"(d[2]), "+f"(d[3])
        : "r"(a[0]), "r"(a[1]), "r"(a[2]), "r"(a[3]), "r"(b[0]), "r"(b[1]));
}

__global__ __launch_bounds__(256, 1)
void lstm_disc_kernel(
    const float* __restrict__ x,      // [B, T]
    const float* __restrict__ hx0,    // [B, H]
    const float* __restrict__ cx0,    // [B, H]
    const float* __restrict__ W_ih,   // [4H, 1]
    const float* __restrict__ W_hh,   // [4H, H]
    const float* __restrict__ b_ih,   // [4H]
    const float* __restrict__ b_hh,   // [4H]
    const float* __restrict__ W_mlp,  // [1, H]
    const float* __restrict__ b_mlp,  // [1]
    float* __restrict__ out)          // [B, 1]
{
    __shared__ float xs[MB][T_STEPS];                       // 32 KB
    __shared__ __align__(16) __half hbuf[2][MB][HSTR];      // 8.5 KB, double-buffered h
    __shared__ float2 wb[4 * HDIM];                         // (W_ih[col], b_ih+b_hh) 4 KB

    const int tid  = threadIdx.x;
    const int w    = tid >> 5;   // warp 0..7: owns j in [16w, 16w+16) of every gate
    const int l    = tid & 31;
    const int qr   = l >> 2;     // 0..7
    const int ql   = l & 3;      // 0..3
    const int brow = blockIdx.x * MB;

    // ---- one-time loads ----
    for (int i = tid; i < MB * T_STEPS; i += 256)
        xs[i / T_STEPS][i % T_STEPS] = x[(size_t)(brow + i / T_STEPS) * T_STEPS + (i % T_STEPS)];
    for (int c2 = tid; c2 < 4 * HDIM; c2 += 256)
        wb[c2] = make_float2(W_ih[c2], b_ih[c2] + b_hh[c2]);
    for (int i = tid; i < MB * HDIM; i += 256) {
        int r = i / HDIM, j = i % HDIM;
        hbuf[0][r][j] = __float2half(hx0[(size_t)(brow + r) * HDIM + j]);
    }

    // W_hh -> f16 B fragments in registers (once). Tile (g, t2) covers
    // n = g*128 + 16w + 8*t2 .. +8, k-tile kk covers k = 16kk .. +16.
    uint32_t Bf[4][2][8][2];
    #pragma unroll
    for (int g = 0; g < 4; ++g)
        #pragma unroll
        for (int t2 = 0; t2 < 2; ++t2)
            #pragma unroll
            for (int kk = 0; kk < 8; ++kk) {
                int n = g * HDIM + w * 16 + t2 * 8 + qr;
                int k = kk * 16 + 2 * ql;
                float2 v0 = *reinterpret_cast<const float2*>(&W_hh[(size_t)n * HDIM + k]);
                float2 v1 = *reinterpret_cast<const float2*>(&W_hh[(size_t)n * HDIM + k + 8]);
                __half2 h0 = __floats2half2_rn(v0.x, v0.y);
                __half2 h1 = __floats2half2_rn(v1.x, v1.y);
                Bf[g][t2][kk][0] = *reinterpret_cast<uint32_t*>(&h0);
                Bf[g][t2][kk][1] = *reinterpret_cast<uint32_t*>(&h1);
            }

    // cell state in registers: c[t2][rr][jj] for (row = qr+8rr, j = 16w+8t2+2ql+jj)
    float cst[2][2][2];
    #pragma unroll
    for (int t2 = 0; t2 < 2; ++t2)
        #pragma unroll
        for (int rr = 0; rr < 2; ++rr)
            #pragma unroll
            for (int jj = 0; jj < 2; ++jj) {
                int r = brow + qr + 8 * rr;
                int j = w * 16 + t2 * 8 + 2 * ql + jj;
                cst[t2][rr][jj] = cx0[(size_t)r * HDIM + j];
            }

    __syncthreads();

    // ---- recurrence ----
    #pragma unroll 1
    for (int t = 0; t < T_STEPS; ++t) {
        const int rb = t & 1, wbuf = rb ^ 1;

        // A fragments: h(t) f16 from SMEM, rows 0..15, k 0..127
        uint32_t A[8][4];
        #pragma unroll
        for (int kk = 0; kk < 8; ++kk) {
            int k0 = kk * 16 + 2 * ql;
            A[kk][0] = *reinterpret_cast<const uint32_t*>(&hbuf[rb][qr][k0]);
            A[kk][1] = *reinterpret_cast<const uint32_t*>(&hbuf[rb][qr + 8][k0]);
            A[kk][2] = *reinterpret_cast<const uint32_t*>(&hbuf[rb][qr][k0 + 8]);
            A[kk][3] = *reinterpret_cast<const uint32_t*>(&hbuf[rb][qr + 8][k0 + 8]);
        }

        // gates = h @ W_hh^T : 64 HMMA per warp
        float acc[4][2][4];
        #pragma unroll
        for (int g = 0; g < 4; ++g)
            #pragma unroll
            for (int t2 = 0; t2 < 2; ++t2) {
                #pragma unroll
                for (int q4 = 0; q4 < 4; ++q4) acc[g][t2][q4] = 0.f;
                #pragma unroll
                for (int kk = 0; kk < 8; ++kk)
                    mma16816(acc[g][t2], A[kk], Bf[g][t2][kk]);
            }

        // epilogue: add input/bias contribution, activations, cell update
        float xr[2] = { xs[qr][t], xs[qr + 8][t] };
        #pragma unroll
        for (int t2 = 0; t2 < 2; ++t2) {
            float hv[2][2];
            #pragma unroll
            for (int jj = 0; jj < 2; ++jj) {
                int j = w * 16 + t2 * 8 + 2 * ql + jj;
                float2 wi = wb[0 * HDIM + j];
                float2 wf = wb[1 * HDIM + j];
                float2 wg = wb[2 * HDIM + j];
                float2 wo = wb[3 * HDIM + j];
                #pragma unroll
                for (int rr = 0; rr < 2; ++rr) {
                    int di = 2 * rr + jj;
                    float gi = acc[0][t2][di] + fmaf(xr[rr], wi.x, wi.y);
                    float gf = acc[1][t2][di] + fmaf(xr[rr], wf.x, wf.y);
                    float gg = acc[2][t2][di] + fmaf(xr[rr], wg.x, wg.y);
                    float go = acc[3][t2][di] + fmaf(xr[rr], wo.x, wo.y);
                    float iv = sigmoid_fast(gi);
                    float fv = sigmoid_fast(gf);
                    float gv = tanh_approx(gg);
                    float ov = sigmoid_fast(go);
                    float c  = fmaf(fv, cst[t2][rr][jj], iv * gv);
                    cst[t2][rr][jj] = c;
                    hv[rr][jj] = ov * tanh_approx(c);
                }
            }
            #pragma unroll
            for (int rr = 0; rr < 2; ++rr) {
                __half2 hp = __floats2half2_rn(hv[rr][0], hv[rr][1]);
                *reinterpret_cast<uint32_t*>(
                    &hbuf[wbuf][qr + 8 * rr][w * 16 + t2 * 8 + 2 * ql]) =
                    *reinterpret_cast<uint32_t*>(&hp);
            }
        }
        __syncthreads();
    }

    // ---- final MLP + sigmoid ----  (h(T) lives in hbuf[0] since T is even)
    if (tid < 128) {
        int r = tid >> 3, q = tid & 7;
        float s = 0.f;
        #pragma unroll
        for (int k = 0; k < 16; ++k) {
            int j = q * 16 + k;
            s = fmaf(__half2float(hbuf[0][r][j]), W_mlp[j], s);
        }
        s += __shfl_xor_sync(0xffffffffu, s, 1);
        s += __shfl_xor_sync(0xffffffffu, s, 2);
        s += __shfl_xor_sync(0xffffffffu, s, 4);
        if (q == 0) {
            float z = s + b_mlp[0];
            out[brow + r] = 1.f / (1.f + __expf(-z));
        }
    }
}

extern "C" void kernel_launch(void* const* d_in, const int* in_sizes, int n_in,
                              void* d_out, int out_size) {
    const float* x     = (const float*)d_in[0];
    const float* hx0   = (const float*)d_in[1];
    const float* cx0   = (const float*)d_in[2];
    const float* W_ih  = (const float*)d_in[3];
    const float* W_hh  = (const float*)d_in[4];
    const float* b_ih  = (const float*)d_in[5];
    const float* b_hh  = (const float*)d_in[6];
    const float* W_mlp = (const float*)d_in[7];
    const float* b_mlp = (const float*)d_in[8];
    float* out = (float*)d_out;

    const int B = out_size;          // 2048
    dim3 grid(B / MB), block(256);
    lstm_disc_kernel<<<grid, block>>>(x, hx0, cx0, W_ih, W_hh, b_ih, b_hh,
                                      W_mlp, b_mlp, out);
}

// round 4
// speedup vs baseline: 1.1183x; 1.1183x over previous
#include <cuda_runtime.h>
#include <cuda_fp16.h>
#include <cstdint>

// LSTM discriminator: B=2048, T=512, H=128, input dim 1.
// Persistent kernel: 128 CTAs x 512 threads (16 warps, 4/SMSP), CTA owns 16 rows.
// Warp w owns gate-column slice j in [8w, 8w+8) of each of the 4 gates.
// W_hh held as f16 mma B-fragments in registers (64 regs/thread).
// h(t) exchanged through double-buffered SMEM (f16), one barrier per step.

#define T_STEPS 512
#define HDIM    128
#define MB      16
#define HSTR    136   // padded stride in halves (272B): LDSM + STS conflict-free

__device__ __forceinline__ float tanh_approx(float x) {
    float y;
    asm("tanh.approx.f32 %0, %1;" : "=f"(y) : "f"(x));
    return y;
}
__device__ __forceinline__ float sigmoid_fast(float x) {
    return fmaf(tanh_approx(0.5f * x), 0.5f, 0.5f);
}

__device__ __forceinline__ void mma16816(float d[4], const uint32_t a[4], const uint32_t b[2]) {
    asm volatile(
        "mma.sync.aligned.m16n8k16.row.col.f32.f16.f16.f32 "
        "{%0,%1,%2,%3}, {%4,%5,%6,%7}, {%8,%9}, {%0,%1,%2,%3};\n"
        : "+f"(d[0]), "+f"(d[1]), "+f"(d[2]), "+f"(d[3])
        : "r"(a[0]), "r"(a[1]), "r"(a[2]), "r"(a[3]), "r"(b[0]), "r"(b[1]));
}

__device__ __forceinline__ void ldsm_x4(uint32_t a[4], uint32_t saddr) {
    asm volatile(
        "ldmatrix.sync.aligned.m8n8.x4.shared.b16 {%0,%1,%2,%3}, [%4];"
        : "=r"(a[0]), "=r"(a[1]), "=r"(a[2]), "=r"(a[3])
        : "r"(saddr));
}

__global__ __launch_bounds__(512, 1)
void lstm_disc_kernel(
    const float* __restrict__ x,      // [B, T]
    const float* __restrict__ hx0,    // [B, H]
    const float* __restrict__ cx0,    // [B, H]
    const float* __restrict__ W_ih,   // [4H, 1]
    const float* __restrict__ W_hh,   // [4H, H]
    const float* __restrict__ b_ih,   // [4H]
    const float* __restrict__ b_hh,   // [4H]
    const float* __restrict__ W_mlp,  // [1, H]
    const float* __restrict__ b_mlp,  // [1]
    float* __restrict__ out)          // [B, 1]
{
    __shared__ float xs[MB][T_STEPS + 1];                   // +1 pad: de-conflict column reads
    __shared__ __align__(16) __half hbuf[2][MB][HSTR];      // double-buffered h (f16)
    __shared__ float2 wb[4 * HDIM];                         // (W_ih[col], b_ih+b_hh)

    const int tid  = threadIdx.x;
    const int w    = tid >> 5;   // warp 0..15: owns j in [8w, 8w+8) of every gate
    const int l    = tid & 31;
    const int qr   = l >> 2;     // 0..7
    const int ql   = l & 3;      // 0..3
    const int brow = blockIdx.x * MB;

    // ---- one-time loads ----
    for (int i = tid; i < MB * T_STEPS; i += 512)
        xs[i / T_STEPS][i % T_STEPS] = x[(size_t)(brow + i / T_STEPS) * T_STEPS + (i % T_STEPS)];
    for (int c2 = tid; c2 < 4 * HDIM; c2 += 512)
        wb[c2] = make_float2(W_ih[c2], b_ih[c2] + b_hh[c2]);
    for (int i = tid; i < MB * HDIM; i += 512) {
        int r = i / HDIM, j = i % HDIM;
        hbuf[0][r][j] = __float2half(hx0[(size_t)(brow + r) * HDIM + j]);
    }

    // W_hh -> f16 B fragments in registers (once). Tile g covers
    // n = g*128 + 8w + qr, k-tile kk covers k = 16kk .. +16.
    uint32_t Bf[4][8][2];
    #pragma unroll
    for (int g = 0; g < 4; ++g)
        #pragma unroll
        for (int kk = 0; kk < 8; ++kk) {
            int n = g * HDIM + w * 8 + qr;
            int k = kk * 16 + 2 * ql;
            float2 v0 = *reinterpret_cast<const float2*>(&W_hh[(size_t)n * HDIM + k]);
            float2 v1 = *reinterpret_cast<const float2*>(&W_hh[(size_t)n * HDIM + k + 8]);
            __half2 h0 = __floats2half2_rn(v0.x, v0.y);
            __half2 h1 = __floats2half2_rn(v1.x, v1.y);
            Bf[g][kk][0] = *reinterpret_cast<uint32_t*>(&h0);
            Bf[g][kk][1] = *reinterpret_cast<uint32_t*>(&h1);
        }

    // cell state in registers: cst[rr][jj] for (row = qr+8rr, j = 8w+2ql+jj)
    float cst[2][2];
    #pragma unroll
    for (int rr = 0; rr < 2; ++rr)
        #pragma unroll
        for (int jj = 0; jj < 2; ++jj) {
            int r = brow + qr + 8 * rr;
            int j = w * 8 + 2 * ql + jj;
            cst[rr][jj] = cx0[(size_t)r * HDIM + j];
        }

    // LDSM source address pattern: lane gives row (l&15), k-half ((l>>4)*8)
    const int lrow = l & 15;
    const int lkof = (l >> 4) * 8;

    __syncthreads();

    // ---- recurrence ----
    #pragma unroll 1
    for (int t = 0; t < T_STEPS; ++t) {
        const int rb = t & 1, wbuf = rb ^ 1;

        float acc[4][4];
        #pragma unroll
        for (int g = 0; g < 4; ++g)
            #pragma unroll
            for (int q4 = 0; q4 < 4; ++q4) acc[g][q4] = 0.f;

        // gates = h @ W_hh^T : 8 LDSM.x4 + 32 HMMA per warp
        #pragma unroll
        for (int kk = 0; kk < 8; ++kk) {
            uint32_t A[4];
            uint32_t saddr = (uint32_t)__cvta_generic_to_shared(
                &hbuf[rb][lrow][kk * 16 + lkof]);
            ldsm_x4(A, saddr);
            #pragma unroll
            for (int g = 0; g < 4; ++g)
                mma16816(acc[g], A, Bf[g][kk]);
        }

        // epilogue: input/bias contribution, activations, cell update
        float xr[2] = { xs[qr][t], xs[qr + 8][t] };
        float hv[2][2];
        #pragma unroll
        for (int jj = 0; jj < 2; ++jj) {
            int j = w * 8 + 2 * ql + jj;
            float2 wi = wb[0 * HDIM + j];
            float2 wf = wb[1 * HDIM + j];
            float2 wg = wb[2 * HDIM + j];
            float2 wo = wb[3 * HDIM + j];
            #pragma unroll
            for (int rr = 0; rr < 2; ++rr) {
                int di = 2 * rr + jj;
                float gi = acc[0][di] + fmaf(xr[rr], wi.x, wi.y);
                float gf = acc[1][di] + fmaf(xr[rr], wf.x, wf.y);
                float gg = acc[2][di] + fmaf(xr[rr], wg.x, wg.y);
                float go = acc[3][di] + fmaf(xr[rr], wo.x, wo.y);
                float iv = sigmoid_fast(gi);
                float fv = sigmoid_fast(gf);
                float gv = tanh_approx(gg);
                float ov = sigmoid_fast(go);
                float c  = fmaf(fv, cst[rr][jj], iv * gv);
                cst[rr][jj] = c;
                hv[rr][jj] = ov * tanh_approx(c);
            }
        }
        #pragma unroll
        for (int rr = 0; rr < 2; ++rr) {
            __half2 hp = __floats2half2_rn(hv[rr][0], hv[rr][1]);
            *reinterpret_cast<uint32_t*>(
                &hbuf[wbuf][qr + 8 * rr][w * 8 + 2 * ql]) =
                *reinterpret_cast<uint32_t*>(&hp);
        }
        __syncthreads();
    }

    // ---- final MLP + sigmoid ----  (h(T) lives in hbuf[0] since T is even)
    if (tid < 128) {
        int r = tid >> 3, q = tid & 7;
        float s = 0.f;
        #pragma unroll
        for (int k = 0; k < 16; ++k) {
            int j = q * 16 + k;
            s = fmaf(__half2float(hbuf[0][r][j]), W_mlp[j], s);
        }
        s += __shfl_xor_sync(0xffffffffu, s, 1);
        s += __shfl_xor_sync(0xffffffffu, s, 2);
        s += __shfl_xor_sync(0xffffffffu, s, 4);
        if (q == 0) {
            float z = s + b_mlp[0];
            out[brow + r] = 1.f / (1.f + __expf(-z));
        }
    }
}

extern "C" void kernel_launch(void* const* d_in, const int* in_sizes, int n_in,
                              void* d_out, int out_size) {
    const float* x     = (const float*)d_in[0];
    const float* hx0   = (const float*)d_in[1];
    const float* cx0   = (const float*)d_in[2];
    const float* W_ih  = (const float*)d_in[3];
    const float* W_hh  = (const float*)d_in[4];
    const float* b_ih  = (const float*)d_in[5];
    const float* b_hh  = (const float*)d_in[6];
    const float* W_mlp = (const float*)d_in[7];
    const float* b_mlp = (const float*)d_in[8];
    float* out = (float*)d_out;

    const int B = out_size;          // 2048
    dim3 grid(B / MB), block(512);
    lstm_disc_kernel<<<grid, block>>>(x, hx0, cx0, W_ih, W_hh, b_ih, b_hh,
                                      W_mlp, b_mlp, out);
}

// round 5
// speedup vs baseline: 1.1515x; 1.0297x over previous
#include <cuda_runtime.h>
#include <cuda_fp16.h>
#include <cstdint>

// LSTM discriminator: B=2048, T=512, H=128, input dim 1.
// Persistent kernel: 128 CTAs x 512 threads (16 warps), CTA owns 16 batch rows.
// Warp w owns gate-column slice j in [8w, 8w+8) of each gate.
// All-f16 datapath: f16-accumulator HMMA (gates arrive packed as half2),
// tanh.approx.f16x2 activations, half2 cell state. One barrier per step.

#define T_STEPS 512
#define HDIM    128
#define MB      16
#define HSTR    136   // padded stride in halves (272B): LDSM + STS conflict-free

__device__ __forceinline__ __half2 tanh2(__half2 x) {
    uint32_t xi = *reinterpret_cast<uint32_t*>(&x), yi;
    asm("tanh.approx.f16x2 %0, %1;" : "=r"(yi) : "r"(xi));
    return *reinterpret_cast<__half2*>(&yi);
}

__device__ __forceinline__ void mma16816_f16(uint32_t d[2], const uint32_t a[4],
                                             const uint32_t b[2]) {
    asm volatile(
        "mma.sync.aligned.m16n8k16.row.col.f16.f16.f16.f16 "
        "{%0,%1}, {%2,%3,%4,%5}, {%6,%7}, {%0,%1};\n"
        : "+r"(d[0]), "+r"(d[1])
        : "r"(a[0]), "r"(a[1]), "r"(a[2]), "r"(a[3]), "r"(b[0]), "r"(b[1]));
}

__device__ __forceinline__ void ldsm_x4(uint32_t a[4], uint32_t saddr) {
    asm volatile(
        "ldmatrix.sync.aligned.m8n8.x4.shared.b16 {%0,%1,%2,%3}, [%4];"
        : "=r"(a[0]), "=r"(a[1]), "=r"(a[2]), "=r"(a[3])
        : "r"(saddr));
}

__global__ __launch_bounds__(512, 1)
void lstm_disc_kernel(
    const float* __restrict__ x,      // [B, T]
    const float* __restrict__ hx0,    // [B, H]
    const float* __restrict__ cx0,    // [B, H]
    const float* __restrict__ W_ih,   // [4H, 1]
    const float* __restrict__ W_hh,   // [4H, H]
    const float* __restrict__ b_ih,   // [4H]
    const float* __restrict__ b_hh,   // [4H]
    const float* __restrict__ W_mlp,  // [1, H]
    const float* __restrict__ b_mlp,  // [1]
    float* __restrict__ out)          // [B, 1]
{
    __shared__ float xs[MB][T_STEPS + 1];
    __shared__ __align__(16) __half hbuf[2][MB][HSTR];
    __shared__ __half2 wih2[4][64];   // W_ih pairs per gate
    __shared__ __half2 bb2[4][64];    // (b_ih + b_hh) pairs per gate

    const int tid  = threadIdx.x;
    const int w    = tid >> 5;   // warp 0..15
    const int l    = tid & 31;
    const int qr   = l >> 2;     // 0..7
    const int ql   = l & 3;      // 0..3
    const int brow = blockIdx.x * MB;

    // ---- one-time loads ----
    for (int i = tid; i < MB * T_STEPS; i += 512)
        xs[i / T_STEPS][i % T_STEPS] = x[(size_t)(brow + i / T_STEPS) * T_STEPS + (i % T_STEPS)];
    for (int i = tid; i < 4 * 64; i += 512) {
        int g = i >> 6, p = i & 63, j = 2 * p;
        wih2[g][p] = __floats2half2_rn(W_ih[g * HDIM + j], W_ih[g * HDIM + j + 1]);
        bb2[g][p]  = __floats2half2_rn(b_ih[g * HDIM + j] + b_hh[g * HDIM + j],
                                       b_ih[g * HDIM + j + 1] + b_hh[g * HDIM + j + 1]);
    }
    for (int i = tid; i < MB * HDIM; i += 512) {
        int r = i / HDIM, j = i % HDIM;
        hbuf[0][r][j] = __float2half(hx0[(size_t)(brow + r) * HDIM + j]);
    }

    // W_hh -> f16 B fragments in registers (once).
    uint32_t Bf[4][8][2];
    #pragma unroll
    for (int g = 0; g < 4; ++g)
        #pragma unroll
        for (int kk = 0; kk < 8; ++kk) {
            int n = g * HDIM + w * 8 + qr;
            int k = kk * 16 + 2 * ql;
            float2 v0 = *reinterpret_cast<const float2*>(&W_hh[(size_t)n * HDIM + k]);
            float2 v1 = *reinterpret_cast<const float2*>(&W_hh[(size_t)n * HDIM + k + 8]);
            __half2 h0 = __floats2half2_rn(v0.x, v0.y);
            __half2 h1 = __floats2half2_rn(v1.x, v1.y);
            Bf[g][kk][0] = *reinterpret_cast<uint32_t*>(&h0);
            Bf[g][kk][1] = *reinterpret_cast<uint32_t*>(&h1);
        }

    // per-thread input-weight / bias pairs (register resident)
    const int jp = w * 4 + ql;    // pair index j/2
    __half2 wi2[4], bi2[4];
    __syncthreads();              // wih2/bb2 ready
    #pragma unroll
    for (int g = 0; g < 4; ++g) { wi2[g] = wih2[g][jp]; bi2[g] = bb2[g][jp]; }

    // cell state as half2: cst[rr] covers (row = qr+8rr, j = 8w+2ql+{0,1})
    __half2 cst[2];
    #pragma unroll
    for (int rr = 0; rr < 2; ++rr) {
        int r = brow + qr + 8 * rr;
        int j = w * 8 + 2 * ql;
        cst[rr] = __floats2half2_rn(cx0[(size_t)r * HDIM + j],
                                    cx0[(size_t)r * HDIM + j + 1]);
    }

    const int lrow = l & 15;
    const int lkof = (l >> 4) * 8;
    const __half2 h05 = __float2half2_rn(0.5f);

    // ---- recurrence ----
    #pragma unroll 1
    for (int t = 0; t < T_STEPS; ++t) {
        const int rb = t & 1, wbuf = rb ^ 1;

        uint32_t acc[4][2];
        #pragma unroll
        for (int g = 0; g < 4; ++g) { acc[g][0] = 0u; acc[g][1] = 0u; }

        // gates(f16) = h @ W_hh^T : 8 LDSM.x4 + 32 HMMA per warp
        #pragma unroll
        for (int kk = 0; kk < 8; ++kk) {
            uint32_t A[4];
            uint32_t saddr = (uint32_t)__cvta_generic_to_shared(
                &hbuf[rb][lrow][kk * 16 + lkof]);
            ldsm_x4(A, saddr);
            #pragma unroll
            for (int g = 0; g < 4; ++g)
                mma16816_f16(acc[g], A, Bf[g][kk]);
        }

        // epilogue, all half2: acc[g][rr] = gates for (row qr+8rr, j-pair)
        #pragma unroll
        for (int rr = 0; rr < 2; ++rr) {
            __half2 xr2 = __float2half2_rn(xs[qr + 8 * rr][t]);
            __half2 gi = __hadd2(*reinterpret_cast<__half2*>(&acc[0][rr]),
                                 __hfma2(xr2, wi2[0], bi2[0]));
            __half2 gf = __hadd2(*reinterpret_cast<__half2*>(&acc[1][rr]),
                                 __hfma2(xr2, wi2[1], bi2[1]));
            __half2 gg = __hadd2(*reinterpret_cast<__half2*>(&acc[2][rr]),
                                 __hfma2(xr2, wi2[2], bi2[2]));
            __half2 go = __hadd2(*reinterpret_cast<__half2*>(&acc[3][rr]),
                                 __hfma2(xr2, wi2[3], bi2[3]));
            __half2 iv = __hfma2(tanh2(__hmul2(gi, h05)), h05, h05);
            __half2 fv = __hfma2(tanh2(__hmul2(gf, h05)), h05, h05);
            __half2 gv = tanh2(gg);
            __half2 ov = __hfma2(tanh2(__hmul2(go, h05)), h05, h05);
            __half2 c  = __hfma2(fv, cst[rr], __hmul2(iv, gv));
            cst[rr] = c;
            __half2 hv = __hmul2(ov, tanh2(c));
            *reinterpret_cast<uint32_t*>(
                &hbuf[wbuf][qr + 8 * rr][w * 8 + 2 * ql]) =
                *reinterpret_cast<uint32_t*>(&hv);
        }
        __syncthreads();
    }

    // ---- final MLP + sigmoid ----  (h(T) in hbuf[0], T even)
    if (tid < 128) {
        int r = tid >> 3, q = tid & 7;
        float s = 0.f;
        #pragma unroll
        for (int k = 0; k < 16; ++k) {
            int j = q * 16 + k;
            s = fmaf(__half2float(hbuf[0][r][j]), W_mlp[j], s);
        }
        s += __shfl_xor_sync(0xffffffffu, s, 1);
        s += __shfl_xor_sync(0xffffffffu, s, 2);
        s += __shfl_xor_sync(0xffffffffu, s, 4);
        if (q == 0) {
            float z = s + b_mlp[0];
            out[brow + r] = 1.f / (1.f + __expf(-z));
        }
    }
}

extern "C" void kernel_launch(void* const* d_in, const int* in_sizes, int n_in,
                              void* d_out, int out_size) {
    const float* x     = (const float*)d_in[0];
    const float* hx0   = (const float*)d_in[1];
    const float* cx0   = (const float*)d_in[2];
    const float* W_ih  = (const float*)d_in[3];
    const float* W_hh  = (const float*)d_in[4];
    const float* b_ih  = (const float*)d_in[5];
    const float* b_hh  = (const float*)d_in[6];
    const float* W_mlp = (const float*)d_in[7];
    const float* b_mlp = (const float*)d_in[8];
    float* out = (float*)d_out;

    const int B = out_size;          // 2048
    dim3 grid(B / MB), block(512);
    lstm_disc_kernel<<<grid, block>>>(x, hx0, cx0, W_ih, W_hh, b_ih, b_hh,
                                      W_mlp, b_mlp, out);
}